// round 14
// baseline (speedup 1.0000x reference)
#include <cuda_runtime.h>

// Problem constants (fixed shapes from the reference setup)
#define NB   16      // batch
#define NT   128     // time
#define NHWC 25088   // 56*56*8 floats per frame
#define NS4  6272    // NHWC / 4 (float4 strips per frame)
#define NC   8       // channels
#define KCH  2       // time chunks
#define TC   (NT / KCH)             // 64 frames per chunk
#define BT   224                    // block threads; NS4 = 28 * 224 exactly
#define NW   (BT / 32)              // 7 warps
#define NBLK_S (NS4 / BT)           // 28 blocks over the spatial strip
#define NBLKS  (NB * KCH * NBLK_S)  // 896 total blocks

// Accumulators (no device allocation allowed -> __device__ globals).
// Zero at module load; the LAST block resets them to zero every launch, so the
// zero-invariant holds across the correctness run and every graph replay.
// fp64 atomics keep the 51M-term sums well inside the 1e-3 rel-err budget.
__device__ double       g_act[NB * NC];
__device__ double       g_tot[NB * NC];
__device__ double       g_ttv;
__device__ unsigned int g_ctr;   // zero at load; last block resets to 0

__global__ __launch_bounds__(BT) void fused_kernel(const float4* __restrict__ x,
                                                   const int*   __restrict__ length,
                                                   const float* __restrict__ count,
                                                   float*       __restrict__ out) {
    const int s4    = blockIdx.x * BT + threadIdx.x;   // always < NS4
    const int chunk = blockIdx.y;
    const int b     = blockIdx.z;
    const int len   = __ldg(&length[b]);
    const int t0    = chunk * TC;
    const float4* base = x + (size_t)b * NT * NS4 + s4;

    float ax = 0.f, ay = 0.f, az = 0.f, aw = 0.f;   // active sums (4 channels)
    float tx = 0.f, ty = 0.f, tz = 0.f, tw = 0.f;   // total sums
    float ttv = 0.f;
    float px = 0.f, py = 0.f, pz = 0.f, pw = 0.f;   // previous masked frame

    if (t0 > 0 && (t0 - 1) < len) {
        float4 p = __ldcs(&base[(size_t)(t0 - 1) * NS4]);
        px = p.x; py = p.y; pz = p.z; pw = p.w;
    }
    #pragma unroll 8
    for (int t = t0; t < t0 + TC; ++t) {
        float4 v = __ldcs(&base[(size_t)t * NS4]);
        tx += v.x; ty += v.y; tz += v.z; tw += v.w;
        float cx, cy, cz, cw;
        if (t < len) {
            cx = v.x; cy = v.y; cz = v.z; cw = v.w;
            ax += v.x; ay += v.y; az += v.z; aw += v.w;
        } else {
            cx = 0.f; cy = 0.f; cz = 0.f; cw = 0.f;
        }
        if (t > 0) {   // skip only the global t=0 (chunk 0, first iter)
            ttv += fabsf(cx - px) + fabsf(cy - py) + fabsf(cz - pz) + fabsf(cw - pw);
        }
        px = cx; py = cy; pz = cz; pw = cw;
    }

    // --- block reduction ---
    #pragma unroll
    for (int m = 16; m >= 1; m >>= 1)
        ttv += __shfl_xor_sync(0xffffffffu, ttv, m);
    // Parity-preserving reduce: even lanes hold channels 0-3, odd lanes 4-7
    #pragma unroll
    for (int m = 2; m <= 16; m <<= 1) {
        ax += __shfl_xor_sync(0xffffffffu, ax, m);
        ay += __shfl_xor_sync(0xffffffffu, ay, m);
        az += __shfl_xor_sync(0xffffffffu, az, m);
        aw += __shfl_xor_sync(0xffffffffu, aw, m);
        tx += __shfl_xor_sync(0xffffffffu, tx, m);
        ty += __shfl_xor_sync(0xffffffffu, ty, m);
        tz += __shfl_xor_sync(0xffffffffu, tz, m);
        tw += __shfl_xor_sync(0xffffffffu, tw, m);
    }

    __shared__ float sh_a[NW][NC];
    __shared__ float sh_t[NW][NC];
    __shared__ float sh_v[NW];
    const int w = threadIdx.x >> 5, lane = threadIdx.x & 31;
    if (lane == 0) {
        sh_a[w][0] = ax; sh_a[w][1] = ay; sh_a[w][2] = az; sh_a[w][3] = aw;
        sh_t[w][0] = tx; sh_t[w][1] = ty; sh_t[w][2] = tz; sh_t[w][3] = tw;
        sh_v[w] = ttv;
    } else if (lane == 1) {
        sh_a[w][4] = ax; sh_a[w][5] = ay; sh_a[w][6] = az; sh_a[w][7] = aw;
        sh_t[w][4] = tx; sh_t[w][5] = ty; sh_t[w][6] = tz; sh_t[w][7] = tw;
    }
    __syncthreads();

    // Per-(b,c) fp64 atomic accumulation: 17 REDGs per block to 129 addresses.
    if (threadIdx.x < NC) {
        const int c = threadIdx.x;
        float sa = 0.f, st = 0.f;
        #pragma unroll
        for (int w2 = 0; w2 < NW; ++w2) { sa += sh_a[w2][c]; st += sh_t[w2][c]; }
        atomicAdd(&g_act[b * NC + c], (double)sa);
        atomicAdd(&g_tot[b * NC + c], (double)st);
    } else if (threadIdx.x == NC) {
        float s = 0.f;
        #pragma unroll
        for (int w2 = 0; w2 < NW; ++w2) s += sh_v[w2];
        atomicAdd(&g_ttv, (double)s);
    }

    // --- threadFenceReduction pattern: only the LAST block runs the tail ---
    __threadfence();                // publish this block's atomic contributions
    __syncthreads();
    __shared__ bool s_last;
    if (threadIdx.x == 0)
        s_last = (atomicAdd(&g_ctr, 1u) == NBLKS - 1);
    __syncthreads();
    if (!s_last) return;

    // --- tail (one block, ~1 us): read 129 doubles, Huber, write, reset ---
    __shared__ float sh_fa[NB * NC];
    __shared__ float sh_ft[NB * NC];
    __shared__ float sh_ftv;
    const int i = threadIdx.x;
    if (i == 0) g_ctr = 0;          // restore invariant for next replay
    if (i < NB * NC) {
        sh_fa[i] = (float)__ldcg(&g_act[i]);
        sh_ft[i] = (float)__ldcg(&g_tot[i]);
        g_act[i] = 0.0;             // reset accumulators for next replay
        g_tot[i] = 0.0;
    } else if (i == NB * NC) {
        sh_ftv = (float)__ldcg(&g_ttv) * 0.1f;
        g_ttv = 0.0;
    }
    __syncthreads();

    if (i < NB) {
        const int bb = i;
        float ah = 0.f, bh = 0.f;
        #pragma unroll
        for (int c = 0; c < NC; ++c) {
            const float aa = sh_fa[bb * NC + c];
            const float tt = sh_ft[bb * NC + c];
            float e  = aa - __ldg(&count[bb * NC + c]);
            float ae = fabsf(e);
            ah += (ae <= 1.f) ? 0.5f * e * e : (ae - 0.5f);
            float eb  = tt - aa;
            float aeb = fabsf(eb);
            bh += (aeb <= 1.f) ? 0.5f * eb * eb : (aeb - 0.5f);
        }
        out[bb] = ah * (1.f / NC) + bh * (1.f / NC) + sh_ftv;
    }
}

extern "C" void kernel_launch(void* const* d_in, const int* in_sizes, int n_in,
                              void* d_out, int out_size) {
    const float* cam    = (const float*)d_in[0];
    const float* count  = (const float*)d_in[1];
    const int*   length = (const int*)d_in[2];
    float*       out    = (float*)d_out;

    dim3 grid(NBLK_S, KCH, NB);   // 28 x 2 x 16 = 896 blocks
    fused_kernel<<<grid, BT>>>((const float4*)cam, length, count, out);
}

// round 15
// speedup vs baseline: 1.0068x; 1.0068x over previous
#include <cuda_runtime.h>

// Problem constants (fixed shapes from the reference setup)
#define NB   16      // batch
#define NT   128     // time
#define NHWC 25088   // 56*56*8 floats per frame
#define NS4  6272    // NHWC / 4 (float4 strips per frame)
#define NC   8       // channels
#define KCH  4       // time chunks (1792 blocks: 2 waves -> good drain overlap)
#define TC   (NT / KCH)             // 32 frames per chunk
#define BT   224                    // block threads; NS4 = 28 * 224 exactly
#define NW   (BT / 32)              // 7 warps
#define NBLK_S (NS4 / BT)           // 28 blocks over the spatial strip
#define NBLKS  (NB * KCH * NBLK_S)  // 1792 total blocks

// Accumulators (no device allocation allowed -> __device__ globals).
// Zero at module load; the LAST block resets them every launch, so the
// zero-invariant holds across the correctness run and every graph replay.
// fp64 atomics keep the 51M-term sums well inside the 1e-3 rel-err budget.
// ttv is per-batch to cap same-address atomic contention at 112 ops/address.
__device__ double       g_act[NB * NC];
__device__ double       g_tot[NB * NC];
__device__ double       g_ttvb[NB];
__device__ unsigned int g_ctr;   // zero at load; last block resets to 0

__global__ __launch_bounds__(BT) void fused_kernel(const float4* __restrict__ x,
                                                   const int*   __restrict__ length,
                                                   const float* __restrict__ count,
                                                   float*       __restrict__ out) {
    const int s4    = blockIdx.x * BT + threadIdx.x;   // always < NS4
    const int chunk = blockIdx.y;
    const int b     = blockIdx.z;
    const int len   = __ldg(&length[b]);
    const int t0    = chunk * TC;
    const float4* base = x + (size_t)b * NT * NS4 + s4;

    float ax = 0.f, ay = 0.f, az = 0.f, aw = 0.f;   // active sums (4 channels)
    float tx = 0.f, ty = 0.f, tz = 0.f, tw = 0.f;   // total sums
    float ttv = 0.f;
    float px = 0.f, py = 0.f, pz = 0.f, pw = 0.f;   // previous masked frame

    if (t0 > 0 && (t0 - 1) < len) {
        float4 p = __ldcs(&base[(size_t)(t0 - 1) * NS4]);
        px = p.x; py = p.y; pz = p.z; pw = p.w;
    }
    #pragma unroll 8
    for (int t = t0; t < t0 + TC; ++t) {
        float4 v = __ldcs(&base[(size_t)t * NS4]);
        tx += v.x; ty += v.y; tz += v.z; tw += v.w;
        float cx, cy, cz, cw;
        if (t < len) {
            cx = v.x; cy = v.y; cz = v.z; cw = v.w;
            ax += v.x; ay += v.y; az += v.z; aw += v.w;
        } else {
            cx = 0.f; cy = 0.f; cz = 0.f; cw = 0.f;
        }
        if (t > 0) {   // skip only the global t=0 (chunk 0, first iter)
            ttv += fabsf(cx - px) + fabsf(cy - py) + fabsf(cz - pz) + fabsf(cw - pw);
        }
        px = cx; py = cy; pz = cz; pw = cw;
    }

    // --- block reduction ---
    #pragma unroll
    for (int m = 16; m >= 1; m >>= 1)
        ttv += __shfl_xor_sync(0xffffffffu, ttv, m);
    // Parity-preserving reduce: even lanes hold channels 0-3, odd lanes 4-7
    #pragma unroll
    for (int m = 2; m <= 16; m <<= 1) {
        ax += __shfl_xor_sync(0xffffffffu, ax, m);
        ay += __shfl_xor_sync(0xffffffffu, ay, m);
        az += __shfl_xor_sync(0xffffffffu, az, m);
        aw += __shfl_xor_sync(0xffffffffu, aw, m);
        tx += __shfl_xor_sync(0xffffffffu, tx, m);
        ty += __shfl_xor_sync(0xffffffffu, ty, m);
        tz += __shfl_xor_sync(0xffffffffu, tz, m);
        tw += __shfl_xor_sync(0xffffffffu, tw, m);
    }

    __shared__ float sh_a[NW][NC];
    __shared__ float sh_t[NW][NC];
    __shared__ float sh_v[NW];
    const int w = threadIdx.x >> 5, lane = threadIdx.x & 31;
    if (lane == 0) {
        sh_a[w][0] = ax; sh_a[w][1] = ay; sh_a[w][2] = az; sh_a[w][3] = aw;
        sh_t[w][0] = tx; sh_t[w][1] = ty; sh_t[w][2] = tz; sh_t[w][3] = tw;
        sh_v[w] = ttv;
    } else if (lane == 1) {
        sh_a[w][4] = ax; sh_a[w][5] = ay; sh_a[w][6] = az; sh_a[w][7] = aw;
        sh_t[w][4] = tx; sh_t[w][5] = ty; sh_t[w][6] = tz; sh_t[w][7] = tw;
    }
    __syncthreads();

    // Per-(b,c) fp64 atomic accumulation: 17 REDGs per block, 112 ops/address.
    if (threadIdx.x < NC) {
        const int c = threadIdx.x;
        float sa = 0.f, st = 0.f;
        #pragma unroll
        for (int w2 = 0; w2 < NW; ++w2) { sa += sh_a[w2][c]; st += sh_t[w2][c]; }
        atomicAdd(&g_act[b * NC + c], (double)sa);
        atomicAdd(&g_tot[b * NC + c], (double)st);
    } else if (threadIdx.x == NC) {
        float s = 0.f;
        #pragma unroll
        for (int w2 = 0; w2 < NW; ++w2) s += sh_v[w2];
        atomicAdd(&g_ttvb[b], (double)s);
    }

    // --- last-block tail via acq_rel counter (no __threadfence stall) ---
    // The release half orders this block's fp64 REDGs before the increment;
    // the acquire half makes all earlier blocks' REDGs visible to the winner.
    __syncthreads();
    __shared__ bool s_last;
    if (threadIdx.x == 0) {
        unsigned int old;
        asm volatile("atom.add.acq_rel.gpu.global.u32 %0, [%1], 1;"
                     : "=r"(old) : "l"(&g_ctr) : "memory");
        s_last = (old == NBLKS - 1);
    }
    __syncthreads();
    if (!s_last) return;

    // --- tail (one block, ~1 us): read 144 doubles, Huber, write, reset ---
    __shared__ float sh_fa[NB * NC];
    __shared__ float sh_ft[NB * NC];
    __shared__ float sh_ftv[NB];
    const int i = threadIdx.x;
    if (i == 0) g_ctr = 0;          // restore invariant for next replay
    if (i < NB * NC) {
        sh_fa[i] = (float)__ldcg(&g_act[i]);
        sh_ft[i] = (float)__ldcg(&g_tot[i]);
        g_act[i] = 0.0;             // reset accumulators for next replay
        g_tot[i] = 0.0;
    } else if (i < NB * NC + NB) {
        const int bb = i - NB * NC;
        sh_ftv[bb] = (float)__ldcg(&g_ttvb[bb]);
        g_ttvb[bb] = 0.0;
    }
    __syncthreads();

    if (i < NB) {
        const int bb = i;
        float tv = 0.f;
        #pragma unroll
        for (int k = 0; k < NB; ++k) tv += sh_ftv[k];
        float ah = 0.f, bh = 0.f;
        #pragma unroll
        for (int c = 0; c < NC; ++c) {
            const float aa = sh_fa[bb * NC + c];
            const float tt = sh_ft[bb * NC + c];
            float e  = aa - __ldg(&count[bb * NC + c]);
            float ae = fabsf(e);
            ah += (ae <= 1.f) ? 0.5f * e * e : (ae - 0.5f);
            float eb  = tt - aa;
            float aeb = fabsf(eb);
            bh += (aeb <= 1.f) ? 0.5f * eb * eb : (aeb - 0.5f);
        }
        out[bb] = ah * (1.f / NC) + bh * (1.f / NC) + tv * 0.1f;
    }
}

extern "C" void kernel_launch(void* const* d_in, const int* in_sizes, int n_in,
                              void* d_out, int out_size) {
    const float* cam    = (const float*)d_in[0];
    const float* count  = (const float*)d_in[1];
    const int*   length = (const int*)d_in[2];
    float*       out    = (float*)d_out;

    dim3 grid(NBLK_S, KCH, NB);   // 28 x 4 x 16 = 1792 blocks
    fused_kernel<<<grid, BT>>>((const float4*)cam, length, count, out);
}